// round 11
// baseline (speedup 1.0000x reference)
#include <cuda_runtime.h>
#include <math.h>

#define NB 4096
#define NI 256
#define NO 256
#define NG 32

constexpr int OT  = 8;    // o-tile per block (8 warps x 1 row)
constexpr int BCH = 4;    // b-chunks per group
constexpr int N_OT = NO / OT;                          // 32
constexpr int MAIN_BLOCKS = BCH * N_OT * NG;           // 4096
constexpr int N_PKL = NG * N_OT;                       // 1024
constexpr int N_GW_BLOCKS = (NO * NI / 4) / 256;       // 64
constexpr int PREP_BLOCKS = N_GW_BLOCKS + 1;           // 65

// ---------------- scratch (device globals; no allocation) ----------------
__device__ float d_gwsA[NO * NI];        // ard_i * sp(gw_rho)
__device__ float d_gmA[NO * NI];         // ard_i * gw_mu
__device__ float d_biasM[NG * NO];
__device__ float d_biasS[NG * NO];
__device__ int   d_perm[NB];
__device__ int   d_goff[NG + 1];
__device__ float d_kl0;                  // alpha/beta/gb terms
__device__ float d_pgw[N_GW_BLOCKS];     // gw KL partials
__device__ float d_pkl[N_PKL];           // per-(g,otile) rw KL partials
__device__ unsigned int d_done;          // zero-init; reset by finalizer

// precise softplus (tiny arrays only)
__device__ __forceinline__ float sp(float x) {
    return fmaxf(x, 0.0f) + log1pf(expf(-fabsf(x)));
}
// fast softplus via MUFU (rel err ~1e-5; tolerance is 1e-3)
__device__ __forceinline__ float spf(float x) {
    return fmaxf(x, 0.0f) + __logf(1.0f + __expf(-fabsf(x)));
}

// shfl-based block reduce for 256 threads; result valid in thread 0
__device__ __forceinline__ float blockReduce256s(float v) {
    __shared__ float red[8];
    #pragma unroll
    for (int s = 16; s; s >>= 1) v += __shfl_down_sync(0xffffffffu, v, s);
    if ((threadIdx.x & 31) == 0) red[threadIdx.x >> 5] = v;
    __syncthreads();
    if (threadIdx.x < 8) {
        v = red[threadIdx.x];
        #pragma unroll
        for (int s = 4; s; s >>= 1) v += __shfl_down_sync(0xffu, v, s);
    }
    return v;
}

// ---------------- k_prep ----------------
// blocks [0,64): gwsA/gmA tables + gw KL.  block 64: small KL + bias + bucketing.
__global__ void __launch_bounds__(256)
k_prep(const float* __restrict__ gwmu, const float* __restrict__ gwrho,
       const float* __restrict__ gbmu, const float* __restrict__ gbrho,
       const float* __restrict__ rbmu, const float* __restrict__ rbrho,
       const float* __restrict__ alpha, const float* __restrict__ beta,
       const int* __restrict__ gids) {
    int bid = blockIdx.x;
    int tid = threadIdx.x;

    if (bid < N_GW_BLOCKS) {
        int idx = bid * 256 + tid;                  // float4 index over O*I/4
        int i4 = idx & (NI / 4 - 1);
        float4 gm = ((const float4*)gwmu)[idx];
        float4 gr = ((const float4*)gwrho)[idx];
        float4 av = ((const float4*)alpha)[i4];
        float4 bv = ((const float4*)beta)[i4];
        float4 ga, gA;
        float kl = 0.0f;
        #pragma unroll
        for (int c = 0; c < 4; c++) {
            float gmv = (c==0)?gm.x:(c==1)?gm.y:(c==2)?gm.z:gm.w;
            float grv = (c==0)?gr.x:(c==1)?gr.y:(c==2)?gr.z:gr.w;
            float avv = (c==0)?av.x:(c==1)?av.y:(c==2)?av.z:av.w;
            float bvv = (c==0)?bv.x:(c==1)?bv.y:(c==2)?bv.z:bv.w;
            float ai = spf(avv) * spf(bvv);
            float gs = spf(grv);
            float lgs = __logf(gs);
            kl += (-lgs + (gs * gs + gmv * gmv) * 0.5f - 0.5f)                  // group prior
                + (-1.41893853320467f - lgs + (lgs * lgs + gs * gs) * 0.5f);    // half-normal
            float gaV = ai * gs;
            float gAV = ai * gmv;
            if (c==0){ga.x=gaV;gA.x=gAV;} else if(c==1){ga.y=gaV;gA.y=gAV;}
            else if (c==2){ga.z=gaV;gA.z=gAV;} else {ga.w=gaV;gA.w=gAV;}
        }
        ((float4*)d_gwsA)[idx] = ga;
        ((float4*)d_gmA)[idx] = gA;
        float tot = blockReduce256s(kl);
        if (tid == 0) d_pgw[bid] = tot;

    } else {
        // ---- small KL + bias tables + bucketing ----
        __shared__ int cnt[NG];
        __shared__ int off[NG];
        float kl = 0.0f;

        kl += sp(alpha[tid]) + sp(beta[tid]);

        float s  = sp(gbrho[tid]);
        float ls = logf(s);
        kl += -1.41893853320467f - ls + (ls * ls + s * s) * 0.5f;

        for (int k = tid; k < NG * NO; k += 256) {
            d_biasM[k] = fmaf(s, rbmu[k], gbmu[tid]);
            d_biasS[k] = s * spf(rbrho[k]);
        }

        float tot = blockReduce256s(kl);
        if (tid == 0) d_kl0 = tot;

        if (tid < NG) cnt[tid] = 0;
        __syncthreads();
        for (int b = tid; b < NB; b += 256)
            atomicAdd(&cnt[gids[b]], 1);
        __syncthreads();
        if (tid == 0) {
            int acc = 0;
            for (int g = 0; g < NG; g++) {
                off[g] = acc; d_goff[g] = acc; acc += cnt[g];
            }
            d_goff[NG] = acc;
        }
        __syncthreads();
        if (tid < NG) cnt[tid] = 0;
        __syncthreads();
        for (int b = tid; b < NB; b += 256) {
            int g = gids[b];
            int r = atomicAdd(&cnt[g], 1);
            d_perm[off[g] + r] = b;
        }
    }
}

// ---------------- k_main: warp-owns-1-row, register S/M, no hot-loop SMEM ----------------
// grid = (BCH, N_OT, NG); 8 warps x 1 output row each; 5 blocks/SM.
__global__ void __launch_bounds__(256, 5)
k_main(const float* __restrict__ epsw, const float* __restrict__ epsb,
       const float* __restrict__ x,
       const float* __restrict__ rwmu, const float* __restrict__ rwrho,
       float* __restrict__ out, float* __restrict__ klout) {
    __shared__ float red8[8];
    __shared__ unsigned s_win;

    int tid  = threadIdx.x;
    int warp = tid >> 5, lane = tid & 31;
    int zc  = blockIdx.x;
    int oy  = blockIdx.y;
    int g   = blockIdx.z;
    int o0  = oy * OT + warp;            // this warp's output row

    // ---- prologue: register-resident ard-folded S/M for 1 row ----
    const float4* rmP = (const float4*)rwmu  + ((size_t)g * NO + o0) * (NI / 4);
    const float4* rrP = (const float4*)rwrho + ((size_t)g * NO + o0) * (NI / 4);
    const float4* gaP = (const float4*)d_gwsA + (size_t)o0 * (NI / 4);
    const float4* gAP = (const float4*)d_gmA  + (size_t)o0 * (NI / 4);

    bool dokl = (zc == 0);
    float kl = 0.0f;

    float4 S[2], M[2];
    #pragma unroll
    for (int sgm = 0; sgm < 2; sgm++) {
        int k = sgm * 32 + lane;
        float4 rm = rmP[k];
        float4 rr = rrP[k];
        float4 ga = gaP[k];
        float4 gA = gAP[k];
        float4 Sv, Mv;
        #pragma unroll
        for (int c = 0; c < 4; c++) {
            float rmv = (c==0)?rm.x:(c==1)?rm.y:(c==2)?rm.z:rm.w;
            float rrv = (c==0)?rr.x:(c==1)?rr.y:(c==2)?rr.z:rr.w;
            float gav = (c==0)?ga.x:(c==1)?ga.y:(c==2)?ga.z:ga.w;
            float gAv = (c==0)?gA.x:(c==1)?gA.y:(c==2)?gA.z:gA.w;
            float rs = spf(rrv);
            float Svv = gav * rs;
            float Mvv = fmaf(gav, rmv, gAv);
            if (c==0){Sv.x=Svv;Mv.x=Mvv;} else if(c==1){Sv.y=Svv;Mv.y=Mvv;}
            else if (c==2){Sv.z=Svv;Mv.z=Mvv;} else {Sv.w=Svv;Mv.w=Mvv;}
            if (dokl) {
                float lrs = __logf(rs);
                kl += -1.41893853320467f - lrs + (rs * rs + rmv * rmv) * 0.5f;
            }
        }
        S[sgm] = Sv; M[sgm] = Mv;
    }

    if (dokl) {
        #pragma unroll
        for (int s2 = 16; s2; s2 >>= 1) kl += __shfl_down_sync(0xffffffffu, kl, s2);
        if (lane == 0) red8[warp] = kl;
        __syncthreads();
        if (warp == 0 && lane < 8) {
            float v = red8[lane];
            #pragma unroll
            for (int s2 = 4; s2; s2 >>= 1) v += __shfl_down_sync(0xffu, v, s2);
            if (lane == 0) d_pkl[g * N_OT + oy] = v;
        }
    }

    // per-warp bias scalars (broadcast loads)
    float bM0 = d_biasM[g * NO + o0];
    float bS0 = d_biasS[g * NO + o0];

    // ---- main stream: every warp iterates all samples of its chunk ----
    int start = d_goff[g];
    int cnt   = d_goff[g + 1] - start;
    int c0 = start + (cnt * zc) / BCH;
    int c1 = start + (cnt * (zc + 1)) / BCH;

    const float4* x4 = (const float4*)x;
    const float4* e4 = (const float4*)epsw;

    for (int si = c0; si < c1; si++) {
        int b = d_perm[si];                       // warp-uniform, cached

        const float4* ep = e4 + ((size_t)b * NO + o0) * (NI / 4);
        const float4* xp = x4 + (size_t)b * (NI / 4);

        // 4 independent loads in flight (2 streaming eps + 2 x L1-shared)
        float4 e0 = __ldcs(ep + lane);
        float4 e1 = __ldcs(ep + lane + 32);
        float4 x0 = xp[lane];
        float4 x1 = xp[lane + 32];

        float acc;
        acc = fmaf(fmaf(S[0].x, e0.x, M[0].x), x0.x, 0.0f);
        acc = fmaf(fmaf(S[0].y, e0.y, M[0].y), x0.y, acc);
        acc = fmaf(fmaf(S[0].z, e0.z, M[0].z), x0.z, acc);
        acc = fmaf(fmaf(S[0].w, e0.w, M[0].w), x0.w, acc);
        acc = fmaf(fmaf(S[1].x, e1.x, M[1].x), x1.x, acc);
        acc = fmaf(fmaf(S[1].y, e1.y, M[1].y), x1.y, acc);
        acc = fmaf(fmaf(S[1].z, e1.z, M[1].z), x1.z, acc);
        acc = fmaf(fmaf(S[1].w, e1.w, M[1].w), x1.w, acc);

        #pragma unroll
        for (int s2 = 16; s2; s2 >>= 1)
            acc += __shfl_down_sync(0xffffffffu, acc, s2);

        if (lane == 0) {
            // 8 warps' lane0 write 8 consecutive floats -> one sector/block/sample
            out[(size_t)b * NO + o0] =
                acc + fmaf(bS0, epsb[(size_t)b * NO + o0], bM0);
        }
    }

    // ---- deterministic KL finalize: last block reduces fixed-order partials ----
    if (tid == 0) {
        __threadfence();
        s_win = (atomicAdd(&d_done, 1u) == MAIN_BLOCKS - 1) ? 1u : 0u;
    }
    __syncthreads();
    if (s_win) {
        __threadfence();
        if (tid < 32) {
            float v = (tid == 0) ? d_kl0 : 0.0f;
            for (int k = tid; k < N_PKL; k += 32) v += d_pkl[k];
            for (int k = tid; k < N_GW_BLOCKS; k += 32) v += d_pgw[k];
            #pragma unroll
            for (int o2 = 16; o2; o2 >>= 1) v += __shfl_down_sync(0xffffffffu, v, o2);
            if (tid == 0) {
                *klout = v;
                d_done = 0;   // reset for next graph replay
            }
        }
    }
}

// ---------------- launch ----------------
extern "C" void kernel_launch(void* const* d_in, const int* in_sizes, int n_in,
                              void* d_out, int out_size) {
    const float* x     = (const float*)d_in[0];
    const float* gwmu  = (const float*)d_in[1];
    const float* gwrho = (const float*)d_in[2];
    const float* gbmu  = (const float*)d_in[3];
    const float* gbrho = (const float*)d_in[4];
    const float* rwmu  = (const float*)d_in[5];
    const float* rwrho = (const float*)d_in[6];
    const float* rbmu  = (const float*)d_in[7];
    const float* rbrho = (const float*)d_in[8];
    const float* alpha = (const float*)d_in[9];
    const float* beta  = (const float*)d_in[10];
    const float* epsw  = (const float*)d_in[11];
    const float* epsb  = (const float*)d_in[12];
    const int*   gids  = (const int*)d_in[13];

    float* out   = (float*)d_out;
    float* klout = out + (out_size - 1);

    k_prep<<<PREP_BLOCKS, 256>>>(gwmu, gwrho, gbmu, gbrho,
                                 rbmu, rbrho, alpha, beta, gids);

    dim3 grid(BCH, N_OT, NG);
    k_main<<<grid, 256>>>(epsw, epsb, x, rwmu, rwrho, out, klout);
}

// round 12
// speedup vs baseline: 1.1272x; 1.1272x over previous
#include <cuda_runtime.h>
#include <math.h>

#define NB 4096
#define NI 256
#define NO 256
#define NG 32

constexpr int OT  = 8;    // o-tile per block (8 warps x 1 row)
constexpr int BCH = 4;    // b-chunks per group
constexpr int N_OT = NO / OT;                          // 32
constexpr int MAIN_BLOCKS = BCH * N_OT * NG;           // 4096
constexpr int N_PKL = NG * N_OT;                       // 1024
constexpr int N_GW_BLOCKS = (NO * NI / 4) / 256;       // 64
constexpr int PREP_BLOCKS = N_GW_BLOCKS + 1;           // 65

// ---------------- scratch (device globals; no allocation) ----------------
__device__ float d_gwsA[NO * NI];        // ard_i * sp(gw_rho)
__device__ float d_gmA[NO * NI];         // ard_i * gw_mu
__device__ float d_biasM[NG * NO];
__device__ float d_biasS[NG * NO];
__device__ int   d_perm[NB];
__device__ int   d_goff[NG + 1];
__device__ float d_kl0;                  // alpha/beta/gb terms
__device__ float d_pgw[N_GW_BLOCKS];     // gw KL partials
__device__ float d_pkl[N_PKL];           // per-(g,otile) rw KL partials
__device__ unsigned int d_done;          // zero-init; reset by finalizer

// precise softplus (tiny arrays only)
__device__ __forceinline__ float sp(float x) {
    return fmaxf(x, 0.0f) + log1pf(expf(-fabsf(x)));
}
// fast softplus via MUFU (rel err ~1e-5; tolerance is 1e-3)
__device__ __forceinline__ float spf(float x) {
    return fmaxf(x, 0.0f) + __logf(1.0f + __expf(-fabsf(x)));
}

// shfl-based block reduce for 256 threads; result valid in thread 0
__device__ __forceinline__ float blockReduce256s(float v) {
    __shared__ float red[8];
    #pragma unroll
    for (int s = 16; s; s >>= 1) v += __shfl_down_sync(0xffffffffu, v, s);
    if ((threadIdx.x & 31) == 0) red[threadIdx.x >> 5] = v;
    __syncthreads();
    if (threadIdx.x < 8) {
        v = red[threadIdx.x];
        #pragma unroll
        for (int s = 4; s; s >>= 1) v += __shfl_down_sync(0xffu, v, s);
    }
    return v;
}

// ---------------- k_prep ----------------
// blocks [0,64): gwsA/gmA tables + gw KL.  block 64: small KL + bias + bucketing.
__global__ void __launch_bounds__(256)
k_prep(const float* __restrict__ gwmu, const float* __restrict__ gwrho,
       const float* __restrict__ gbmu, const float* __restrict__ gbrho,
       const float* __restrict__ rbmu, const float* __restrict__ rbrho,
       const float* __restrict__ alpha, const float* __restrict__ beta,
       const int* __restrict__ gids) {
    int bid = blockIdx.x;
    int tid = threadIdx.x;

    if (bid < N_GW_BLOCKS) {
        int idx = bid * 256 + tid;                  // float4 index over O*I/4
        int i4 = idx & (NI / 4 - 1);
        float4 gm = ((const float4*)gwmu)[idx];
        float4 gr = ((const float4*)gwrho)[idx];
        float4 av = ((const float4*)alpha)[i4];
        float4 bv = ((const float4*)beta)[i4];
        float4 ga, gA;
        float kl = 0.0f;
        #pragma unroll
        for (int c = 0; c < 4; c++) {
            float gmv = (c==0)?gm.x:(c==1)?gm.y:(c==2)?gm.z:gm.w;
            float grv = (c==0)?gr.x:(c==1)?gr.y:(c==2)?gr.z:gr.w;
            float avv = (c==0)?av.x:(c==1)?av.y:(c==2)?av.z:av.w;
            float bvv = (c==0)?bv.x:(c==1)?bv.y:(c==2)?bv.z:bv.w;
            float ai = spf(avv) * spf(bvv);
            float gs = spf(grv);
            float lgs = __logf(gs);
            kl += (-lgs + (gs * gs + gmv * gmv) * 0.5f - 0.5f)                  // group prior
                + (-1.41893853320467f - lgs + (lgs * lgs + gs * gs) * 0.5f);    // half-normal
            float gaV = ai * gs;
            float gAV = ai * gmv;
            if (c==0){ga.x=gaV;gA.x=gAV;} else if(c==1){ga.y=gaV;gA.y=gAV;}
            else if (c==2){ga.z=gaV;gA.z=gAV;} else {ga.w=gaV;gA.w=gAV;}
        }
        ((float4*)d_gwsA)[idx] = ga;
        ((float4*)d_gmA)[idx] = gA;
        float tot = blockReduce256s(kl);
        if (tid == 0) d_pgw[bid] = tot;

    } else {
        // ---- small KL + bias tables + bucketing ----
        __shared__ int cnt[NG];
        __shared__ int off[NG];
        float kl = 0.0f;

        kl += sp(alpha[tid]) + sp(beta[tid]);

        float s  = sp(gbrho[tid]);
        float ls = logf(s);
        kl += -1.41893853320467f - ls + (ls * ls + s * s) * 0.5f;

        for (int k = tid; k < NG * NO; k += 256) {
            d_biasM[k] = fmaf(s, rbmu[k], gbmu[tid]);
            d_biasS[k] = s * spf(rbrho[k]);
        }

        float tot = blockReduce256s(kl);
        if (tid == 0) d_kl0 = tot;

        if (tid < NG) cnt[tid] = 0;
        __syncthreads();
        for (int b = tid; b < NB; b += 256)
            atomicAdd(&cnt[gids[b]], 1);
        __syncthreads();
        if (tid == 0) {
            int acc = 0;
            for (int g = 0; g < NG; g++) {
                off[g] = acc; d_goff[g] = acc; acc += cnt[g];
            }
            d_goff[NG] = acc;
        }
        __syncthreads();
        if (tid < NG) cnt[tid] = 0;
        __syncthreads();
        for (int b = tid; b < NB; b += 256) {
            int g = gids[b];
            int r = atomicAdd(&cnt[g], 1);
            d_perm[off[g] + r] = b;
        }
    }
}

// ---------------- k_main: warp-owns-1-row, register S/M, software-pipelined eps ----------------
// grid = (BCH, N_OT, NG); 8 warps x 1 output row each.
__global__ void __launch_bounds__(256, 4)
k_main(const float* __restrict__ epsw, const float* __restrict__ epsb,
       const float* __restrict__ x,
       const float* __restrict__ rwmu, const float* __restrict__ rwrho,
       float* __restrict__ out, float* __restrict__ klout) {
    __shared__ float red8[8];
    __shared__ unsigned s_win;

    int tid  = threadIdx.x;
    int warp = tid >> 5, lane = tid & 31;
    int zc  = blockIdx.x;
    int oy  = blockIdx.y;
    int g   = blockIdx.z;
    int o0  = oy * OT + warp;            // this warp's output row

    // ---- prologue: register-resident ard-folded S/M for 1 row ----
    const float4* rmP = (const float4*)rwmu  + ((size_t)g * NO + o0) * (NI / 4);
    const float4* rrP = (const float4*)rwrho + ((size_t)g * NO + o0) * (NI / 4);
    const float4* gaP = (const float4*)d_gwsA + (size_t)o0 * (NI / 4);
    const float4* gAP = (const float4*)d_gmA  + (size_t)o0 * (NI / 4);

    bool dokl = (zc == 0);
    float kl = 0.0f;

    float4 S[2], M[2];
    #pragma unroll
    for (int sgm = 0; sgm < 2; sgm++) {
        int k = sgm * 32 + lane;
        float4 rm = rmP[k];
        float4 rr = rrP[k];
        float4 ga = gaP[k];
        float4 gA = gAP[k];
        float4 Sv, Mv;
        #pragma unroll
        for (int c = 0; c < 4; c++) {
            float rmv = (c==0)?rm.x:(c==1)?rm.y:(c==2)?rm.z:rm.w;
            float rrv = (c==0)?rr.x:(c==1)?rr.y:(c==2)?rr.z:rr.w;
            float gav = (c==0)?ga.x:(c==1)?ga.y:(c==2)?ga.z:ga.w;
            float gAv = (c==0)?gA.x:(c==1)?gA.y:(c==2)?gA.z:gA.w;
            float rs = spf(rrv);
            float Svv = gav * rs;
            float Mvv = fmaf(gav, rmv, gAv);
            if (c==0){Sv.x=Svv;Mv.x=Mvv;} else if(c==1){Sv.y=Svv;Mv.y=Mvv;}
            else if (c==2){Sv.z=Svv;Mv.z=Mvv;} else {Sv.w=Svv;Mv.w=Mvv;}
            if (dokl) {
                float lrs = __logf(rs);
                kl += -1.41893853320467f - lrs + (rs * rs + rmv * rmv) * 0.5f;
            }
        }
        S[sgm] = Sv; M[sgm] = Mv;
    }

    if (dokl) {
        #pragma unroll
        for (int s2 = 16; s2; s2 >>= 1) kl += __shfl_down_sync(0xffffffffu, kl, s2);
        if (lane == 0) red8[warp] = kl;
        __syncthreads();
        if (warp == 0 && lane < 8) {
            float v = red8[lane];
            #pragma unroll
            for (int s2 = 4; s2; s2 >>= 1) v += __shfl_down_sync(0xffu, v, s2);
            if (lane == 0) d_pkl[g * N_OT + oy] = v;
        }
    }

    // per-warp bias scalars (broadcast loads)
    float bM0 = d_biasM[g * NO + o0];
    float bS0 = d_biasS[g * NO + o0];

    // ---- main stream: software-pipelined over samples ----
    int start = d_goff[g];
    int cnt   = d_goff[g + 1] - start;
    int c0 = start + (cnt * zc) / BCH;
    int c1 = start + (cnt * (zc + 1)) / BCH;

    const float4* x4 = (const float4*)x;
    const float4* e4 = (const float4*)epsw;

    if (c0 < c1) {
        // stage 0: prefetch first sample's perm + eps
        int b = d_perm[c0];
        {
            const float4* ep = e4 + ((size_t)b * NO + o0) * (NI / 4);
            // (loads issued below via e0/e1 init)
        }
        const float4* ep0 = e4 + ((size_t)b * NO + o0) * (NI / 4);
        float4 e0 = __ldcs(ep0 + lane);
        float4 e1 = __ldcs(ep0 + lane + 32);

        #pragma unroll 1
        for (int si = c0; si < c1; si++) {
            int   cb  = b;
            float4 ce0 = e0;
            float4 ce1 = e1;

            // prefetch next sample's perm + eps BEFORE the compute tail
            if (si + 1 < c1) {
                b = d_perm[si + 1];
                const float4* epn = e4 + ((size_t)b * NO + o0) * (NI / 4);
                e0 = __ldcs(epn + lane);
                e1 = __ldcs(epn + lane + 32);
            }

            const float4* xp = x4 + (size_t)cb * (NI / 4);
            float4 x0 = xp[lane];
            float4 x1 = xp[lane + 32];

            float acc;
            acc = fmaf(fmaf(S[0].x, ce0.x, M[0].x), x0.x, 0.0f);
            acc = fmaf(fmaf(S[0].y, ce0.y, M[0].y), x0.y, acc);
            acc = fmaf(fmaf(S[0].z, ce0.z, M[0].z), x0.z, acc);
            acc = fmaf(fmaf(S[0].w, ce0.w, M[0].w), x0.w, acc);
            acc = fmaf(fmaf(S[1].x, ce1.x, M[1].x), x1.x, acc);
            acc = fmaf(fmaf(S[1].y, ce1.y, M[1].y), x1.y, acc);
            acc = fmaf(fmaf(S[1].z, ce1.z, M[1].z), x1.z, acc);
            acc = fmaf(fmaf(S[1].w, ce1.w, M[1].w), x1.w, acc);

            #pragma unroll
            for (int s2 = 16; s2; s2 >>= 1)
                acc += __shfl_down_sync(0xffffffffu, acc, s2);

            if (lane == 0) {
                // 8 warps' lane0 write 8 consecutive floats
                out[(size_t)cb * NO + o0] =
                    acc + fmaf(bS0, epsb[(size_t)cb * NO + o0], bM0);
            }
        }
    }

    // ---- deterministic KL finalize: last block reduces fixed-order partials ----
    if (tid == 0) {
        __threadfence();
        s_win = (atomicAdd(&d_done, 1u) == MAIN_BLOCKS - 1) ? 1u : 0u;
    }
    __syncthreads();
    if (s_win) {
        __threadfence();
        if (tid < 32) {
            float v = (tid == 0) ? d_kl0 : 0.0f;
            for (int k = tid; k < N_PKL; k += 32) v += d_pkl[k];
            for (int k = tid; k < N_GW_BLOCKS; k += 32) v += d_pgw[k];
            #pragma unroll
            for (int o2 = 16; o2; o2 >>= 1) v += __shfl_down_sync(0xffffffffu, v, o2);
            if (tid == 0) {
                *klout = v;
                d_done = 0;   // reset for next graph replay
            }
        }
    }
}

// ---------------- launch ----------------
extern "C" void kernel_launch(void* const* d_in, const int* in_sizes, int n_in,
                              void* d_out, int out_size) {
    const float* x     = (const float*)d_in[0];
    const float* gwmu  = (const float*)d_in[1];
    const float* gwrho = (const float*)d_in[2];
    const float* gbmu  = (const float*)d_in[3];
    const float* gbrho = (const float*)d_in[4];
    const float* rwmu  = (const float*)d_in[5];
    const float* rwrho = (const float*)d_in[6];
    const float* rbmu  = (const float*)d_in[7];
    const float* rbrho = (const float*)d_in[8];
    const float* alpha = (const float*)d_in[9];
    const float* beta  = (const float*)d_in[10];
    const float* epsw  = (const float*)d_in[11];
    const float* epsb  = (const float*)d_in[12];
    const int*   gids  = (const int*)d_in[13];

    float* out   = (float*)d_out;
    float* klout = out + (out_size - 1);

    k_prep<<<PREP_BLOCKS, 256>>>(gwmu, gwrho, gbmu, gbrho,
                                 rbmu, rbrho, alpha, beta, gids);

    dim3 grid(BCH, N_OT, NG);
    k_main<<<grid, 256>>>(epsw, epsb, x, rwmu, rwrho, out, klout);
}

// round 13
// speedup vs baseline: 1.1644x; 1.0331x over previous
#include <cuda_runtime.h>
#include <math.h>

#define NB 4096
#define NI 256
#define NO 256
#define NG 32

constexpr int OT  = 16;   // o-tile per block
constexpr int BCH = 4;    // b-chunks per group
constexpr int N_OT = NO / OT;                          // 16
constexpr int MAIN_BLOCKS = BCH * N_OT * NG;           // 2048
constexpr int N_PKL = NG * N_OT;                       // 512
constexpr int N_GW_BLOCKS = (NO * NI / 4) / 256;       // 64
constexpr int PREP_BLOCKS = N_GW_BLOCKS + 1;           // 65

// ---------------- scratch (device globals; no allocation) ----------------
__device__ float d_gwsA[NO * NI];        // ard_i * sp(gw_rho)
__device__ float d_gmA[NO * NI];         // ard_i * gw_mu
__device__ float d_biasM[NG * NO];
__device__ float d_biasS[NG * NO];
__device__ int   d_perm[NB];
__device__ int   d_goff[NG + 1];
__device__ float d_kl0;                  // alpha/beta/gb terms
__device__ float d_pgw[N_GW_BLOCKS];     // gw KL partials
__device__ float d_pkl[N_PKL];           // per-(g,otile) rw KL partials
__device__ unsigned int d_done;          // zero-init; reset by finalizer

// precise softplus (tiny arrays only)
__device__ __forceinline__ float sp(float x) {
    return fmaxf(x, 0.0f) + log1pf(expf(-fabsf(x)));
}
// fast softplus via MUFU (rel err ~1e-5; tolerance is 1e-3)
__device__ __forceinline__ float spf(float x) {
    return fmaxf(x, 0.0f) + __logf(1.0f + __expf(-fabsf(x)));
}

// shfl-based block reduce for 256 threads; result valid in thread 0
__device__ __forceinline__ float blockReduce256s(float v) {
    __shared__ float red[8];
    #pragma unroll
    for (int s = 16; s; s >>= 1) v += __shfl_down_sync(0xffffffffu, v, s);
    if ((threadIdx.x & 31) == 0) red[threadIdx.x >> 5] = v;
    __syncthreads();
    if (threadIdx.x < 8) {
        v = red[threadIdx.x];
        #pragma unroll
        for (int s = 4; s; s >>= 1) v += __shfl_down_sync(0xffu, v, s);
    }
    return v;
}

// ---------------- k_prep ----------------
// blocks [0,64): gwsA/gmA tables + gw KL.  block 64: small KL + bias + bucketing.
__global__ void __launch_bounds__(256)
k_prep(const float* __restrict__ gwmu, const float* __restrict__ gwrho,
       const float* __restrict__ gbmu, const float* __restrict__ gbrho,
       const float* __restrict__ rbmu, const float* __restrict__ rbrho,
       const float* __restrict__ alpha, const float* __restrict__ beta,
       const int* __restrict__ gids) {
    int bid = blockIdx.x;
    int tid = threadIdx.x;

    if (bid < N_GW_BLOCKS) {
        int idx = bid * 256 + tid;                  // float4 index over O*I/4
        int i4 = idx & (NI / 4 - 1);
        float4 gm = ((const float4*)gwmu)[idx];
        float4 gr = ((const float4*)gwrho)[idx];
        float4 av = ((const float4*)alpha)[i4];
        float4 bv = ((const float4*)beta)[i4];
        float4 ga, gA;
        float kl = 0.0f;
        #pragma unroll
        for (int c = 0; c < 4; c++) {
            float gmv = (c==0)?gm.x:(c==1)?gm.y:(c==2)?gm.z:gm.w;
            float grv = (c==0)?gr.x:(c==1)?gr.y:(c==2)?gr.z:gr.w;
            float avv = (c==0)?av.x:(c==1)?av.y:(c==2)?av.z:av.w;
            float bvv = (c==0)?bv.x:(c==1)?bv.y:(c==2)?bv.z:bv.w;
            float ai = spf(avv) * spf(bvv);
            float gs = spf(grv);
            float lgs = __logf(gs);
            kl += (-lgs + (gs * gs + gmv * gmv) * 0.5f - 0.5f)
                + (-1.41893853320467f - lgs + (lgs * lgs + gs * gs) * 0.5f);
            float gaV = ai * gs;
            float gAV = ai * gmv;
            if (c==0){ga.x=gaV;gA.x=gAV;} else if(c==1){ga.y=gaV;gA.y=gAV;}
            else if (c==2){ga.z=gaV;gA.z=gAV;} else {ga.w=gaV;gA.w=gAV;}
        }
        ((float4*)d_gwsA)[idx] = ga;
        ((float4*)d_gmA)[idx] = gA;
        float tot = blockReduce256s(kl);
        if (tid == 0) d_pgw[bid] = tot;

    } else {
        __shared__ int cnt[NG];
        __shared__ int off[NG];
        float kl = 0.0f;

        kl += sp(alpha[tid]) + sp(beta[tid]);

        float s  = sp(gbrho[tid]);
        float ls = logf(s);
        kl += -1.41893853320467f - ls + (ls * ls + s * s) * 0.5f;

        for (int k = tid; k < NG * NO; k += 256) {
            d_biasM[k] = fmaf(s, rbmu[k], gbmu[tid]);
            d_biasS[k] = s * spf(rbrho[k]);
        }

        float tot = blockReduce256s(kl);
        if (tid == 0) d_kl0 = tot;

        if (tid < NG) cnt[tid] = 0;
        __syncthreads();
        for (int b = tid; b < NB; b += 256)
            atomicAdd(&cnt[gids[b]], 1);
        __syncthreads();
        if (tid == 0) {
            int acc = 0;
            for (int g = 0; g < NG; g++) {
                off[g] = acc; d_goff[g] = acc; acc += cnt[g];
            }
            d_goff[NG] = acc;
        }
        __syncthreads();
        if (tid < NG) cnt[tid] = 0;
        __syncthreads();
        for (int b = tid; b < NB; b += 256) {
            int g = gids[b];
            int r = atomicAdd(&cnt[g], 1);
            d_perm[off[g] + r] = b;
        }
    }
}

// ---------------- k_main: round-8 structure + eps loads hoisted past shfl tail ----------------
// grid = (BCH, N_OT, NG)
__global__ void __launch_bounds__(256, 4)
k_main(const float* __restrict__ epsw, const float* __restrict__ epsb,
       const float* __restrict__ x,
       const float* __restrict__ rwmu, const float* __restrict__ rwrho,
       float* __restrict__ out, float* __restrict__ klout) {
    __shared__ __align__(16) float sS[OT * NI];
    __shared__ __align__(16) float sM[OT * NI];
    __shared__ float sbM[OT];
    __shared__ float sbS[OT];
    __shared__ float stage[8][OT];
    __shared__ unsigned s_win;

    int tid = threadIdx.x;
    int zc  = blockIdx.x;
    int oy  = blockIdx.y;
    int g   = blockIdx.z;
    int ob  = oy * OT;

    // ---- stage ard-folded M/S tile; z==0 also does rw KL ----
    const float4* rm4 = (const float4*)(rwmu + ((size_t)g * NO + ob) * NI);
    const float4* rr4 = (const float4*)(rwrho + ((size_t)g * NO + ob) * NI);
    const float4* ga4 = (const float4*)(d_gwsA + (size_t)ob * NI);
    const float4* gA4 = (const float4*)(d_gmA + (size_t)ob * NI);

    bool dokl = (zc == 0);
    float kl = 0.0f;

    #pragma unroll 1
    for (int k = tid; k < OT * NI / 4; k += 256) {
        float4 rm = rm4[k];
        float4 rr = rr4[k];
        float4 ga = ga4[k];
        float4 gA = gA4[k];
        float4 Mv, Sv;
        #pragma unroll
        for (int c = 0; c < 4; c++) {
            float rmv = (c==0)?rm.x:(c==1)?rm.y:(c==2)?rm.z:rm.w;
            float rrv = (c==0)?rr.x:(c==1)?rr.y:(c==2)?rr.z:rr.w;
            float gav = (c==0)?ga.x:(c==1)?ga.y:(c==2)?ga.z:ga.w;
            float gAv = (c==0)?gA.x:(c==1)?gA.y:(c==2)?gA.z:gA.w;
            float rs = spf(rrv);
            float Svv = gav * rs;
            float Mvv = fmaf(gav, rmv, gAv);
            if (c==0){Sv.x=Svv;Mv.x=Mvv;} else if(c==1){Sv.y=Svv;Mv.y=Mvv;}
            else if (c==2){Sv.z=Svv;Mv.z=Mvv;} else {Sv.w=Svv;Mv.w=Mvv;}
            if (dokl) {
                float lrs = __logf(rs);
                kl += -1.41893853320467f - lrs + (rs * rs + rmv * rmv) * 0.5f;
            }
        }
        ((float4*)sS)[k] = Sv;
        ((float4*)sM)[k] = Mv;
    }
    if (dokl) {
        float tot = blockReduce256s(kl);
        if (tid == 0) d_pkl[g * N_OT + oy] = tot;
    }
    if (tid < OT) {
        sbM[tid] = d_biasM[g * NO + ob + tid];
        sbS[tid] = d_biasS[g * NO + ob + tid];
    }
    __syncthreads();

    int start = d_goff[g];
    int cnt   = d_goff[g + 1] - start;
    int c0 = start + (cnt * zc) / BCH;
    int c1 = start + (cnt * (zc + 1)) / BCH;

    int warp = tid >> 5, lane = tid & 31;
    const float4* e4 = (const float4*)epsw;
    const float4* x4 = (const float4*)x;

    int si = c0 + warp;
    if (si < c1) {
        int bcur = d_perm[si];
        const float4* ep = e4 + ((size_t)bcur * NO + ob) * (NI / 4);
        // preload first ol-pair
        float4 e00 = __ldcs(ep + lane);
        float4 e01 = __ldcs(ep + lane + 32);
        float4 e10 = __ldcs(ep + (NI / 4) + lane);
        float4 e11 = __ldcs(ep + (NI / 4) + lane + 32);
        const float4* xp = x4 + (size_t)bcur * (NI / 4);
        float4 x0 = xp[lane];
        float4 x1 = xp[lane + 32];

        while (true) {
            int bout = bcur;
            int snext = si + 8;
            int bnext = (snext < c1) ? d_perm[snext] : 0;

            #pragma unroll 1
            for (int ol = 0; ol < OT; ol += 2) {
                const float4* SpA = (const float4*)(sS + ol * NI);
                const float4* MpA = (const float4*)(sM + ol * NI);
                float4 s0 = SpA[lane], m0 = MpA[lane];
                float4 s1 = SpA[lane + 32], m1 = MpA[lane + 32];

                float accA;
                accA = fmaf(fmaf(s0.x, e00.x, m0.x), x0.x, 0.0f);
                accA = fmaf(fmaf(s0.y, e00.y, m0.y), x0.y, accA);
                accA = fmaf(fmaf(s0.z, e00.z, m0.z), x0.z, accA);
                accA = fmaf(fmaf(s0.w, e00.w, m0.w), x0.w, accA);
                accA = fmaf(fmaf(s1.x, e01.x, m1.x), x1.x, accA);
                accA = fmaf(fmaf(s1.y, e01.y, m1.y), x1.y, accA);
                accA = fmaf(fmaf(s1.z, e01.z, m1.z), x1.z, accA);
                accA = fmaf(fmaf(s1.w, e01.w, m1.w), x1.w, accA);

                const float4* SpB = (const float4*)(sS + (ol + 1) * NI);
                const float4* MpB = (const float4*)(sM + (ol + 1) * NI);
                s0 = SpB[lane]; m0 = MpB[lane];
                s1 = SpB[lane + 32]; m1 = MpB[lane + 32];

                float accB;
                accB = fmaf(fmaf(s0.x, e10.x, m0.x), x0.x, 0.0f);
                accB = fmaf(fmaf(s0.y, e10.y, m0.y), x0.y, accB);
                accB = fmaf(fmaf(s0.z, e10.z, m0.z), x0.z, accB);
                accB = fmaf(fmaf(s0.w, e10.w, m0.w), x0.w, accB);
                accB = fmaf(fmaf(s1.x, e11.x, m1.x), x1.x, accB);
                accB = fmaf(fmaf(s1.y, e11.y, m1.y), x1.y, accB);
                accB = fmaf(fmaf(s1.z, e11.z, m1.z), x1.z, accB);
                accB = fmaf(fmaf(s1.w, e11.w, m1.w), x1.w, accB);

                // ---- prefetch NEXT ol-pair (or next sample) BEFORE shfl tail ----
                // reuses e00..e11/x0/x1 registers (WAR; eps just consumed above)
                if (ol + 2 < OT) {
                    const float4* epn = ep + (ol + 2) * (NI / 4);
                    e00 = __ldcs(epn + lane);
                    e01 = __ldcs(epn + lane + 32);
                    e10 = __ldcs(epn + (NI / 4) + lane);
                    e11 = __ldcs(epn + (NI / 4) + lane + 32);
                } else if (snext < c1) {
                    ep = e4 + ((size_t)bnext * NO + ob) * (NI / 4);
                    e00 = __ldcs(ep + lane);
                    e01 = __ldcs(ep + lane + 32);
                    e10 = __ldcs(ep + (NI / 4) + lane);
                    e11 = __ldcs(ep + (NI / 4) + lane + 32);
                    const float4* xpn = x4 + (size_t)bnext * (NI / 4);
                    x0 = xpn[lane];
                    x1 = xpn[lane + 32];
                }

                // interleaved shfl trees (loads above are now in flight)
                #pragma unroll
                for (int o2 = 16; o2; o2 >>= 1) {
                    accA += __shfl_down_sync(0xffffffffu, accA, o2);
                    accB += __shfl_down_sync(0xffffffffu, accB, o2);
                }
                if (lane == 0) {
                    stage[warp][ol] = accA;
                    stage[warp][ol + 1] = accB;
                }
            }
            __syncwarp();

            // coalesced epilogue for the finished sample
            if (lane < OT) {
                float bo = fmaf(sbS[lane], epsb[(size_t)bout * NO + ob + lane], sbM[lane]);
                out[(size_t)bout * NO + ob + lane] = stage[warp][lane] + bo;
            }
            __syncwarp();

            if (snext >= c1) break;
            si = snext;
            bcur = bnext;
        }
    }

    // ---- deterministic KL finalize: last block reduces fixed-order partials ----
    if (tid == 0) {
        __threadfence();
        s_win = (atomicAdd(&d_done, 1u) == MAIN_BLOCKS - 1) ? 1u : 0u;
    }
    __syncthreads();
    if (s_win) {
        __threadfence();
        if (tid < 32) {
            float v = (tid == 0) ? d_kl0 : 0.0f;
            for (int k = tid; k < N_PKL; k += 32) v += d_pkl[k];
            for (int k = tid; k < N_GW_BLOCKS; k += 32) v += d_pgw[k];
            #pragma unroll
            for (int o2 = 16; o2; o2 >>= 1) v += __shfl_down_sync(0xffffffffu, v, o2);
            if (tid == 0) {
                *klout = v;
                d_done = 0;   // reset for next graph replay
            }
        }
    }
}

// ---------------- launch ----------------
extern "C" void kernel_launch(void* const* d_in, const int* in_sizes, int n_in,
                              void* d_out, int out_size) {
    const float* x     = (const float*)d_in[0];
    const float* gwmu  = (const float*)d_in[1];
    const float* gwrho = (const float*)d_in[2];
    const float* gbmu  = (const float*)d_in[3];
    const float* gbrho = (const float*)d_in[4];
    const float* rbmu  = (const float*)d_in[7];
    const float* rbrho = (const float*)d_in[8];
    const float* rwmu  = (const float*)d_in[5];
    const float* rwrho = (const float*)d_in[6];
    const float* alpha = (const float*)d_in[9];
    const float* beta  = (const float*)d_in[10];
    const float* epsw  = (const float*)d_in[11];
    const float* epsb  = (const float*)d_in[12];
    const int*   gids  = (const int*)d_in[13];

    float* out   = (float*)d_out;
    float* klout = out + (out_size - 1);

    k_prep<<<PREP_BLOCKS, 256>>>(gwmu, gwrho, gbmu, gbrho,
                                 rbmu, rbrho, alpha, beta, gids);

    dim3 grid(BCH, N_OT, NG);
    k_main<<<grid, 256>>>(epsw, epsb, x, rwmu, rwrho, out, klout);
}

// round 14
// speedup vs baseline: 1.1771x; 1.0109x over previous
#include <cuda_runtime.h>
#include <math.h>

#define NB 4096
#define NI 256
#define NO 256
#define NG 32

constexpr int OT  = 16;   // o-tile per block
constexpr int BCH = 4;    // b-chunks per group
constexpr int N_OT = NO / OT;                          // 16
constexpr int NTILES = BCH * N_OT * NG;                // 2048
constexpr int NBLK = 592;                              // 148 SMs x 4 blocks
constexpr int N_PKL = NG * N_OT;                       // 512
constexpr int N_GW_BLOCKS = (NO * NI / 4) / 256;       // 64
constexpr int PREP_BLOCKS = N_GW_BLOCKS + 1;           // 65

// ---------------- scratch (device globals; no allocation) ----------------
__device__ float d_gwsA[NO * NI];        // ard_i * sp(gw_rho)
__device__ float d_gmA[NO * NI];         // ard_i * gw_mu
__device__ float d_biasM[NG * NO];
__device__ float d_biasS[NG * NO];
__device__ int   d_perm[NB];
__device__ int   d_goff[NG + 1];
__device__ float d_kl0;                  // alpha/beta/gb terms
__device__ float d_pgw[N_GW_BLOCKS];     // gw KL partials
__device__ float d_pkl[N_PKL];           // per-(g,otile) rw KL partials
__device__ unsigned int d_done;          // zero-init; reset by finalizer
__device__ unsigned int d_work;          // zero-init; reset by finalizer

// precise softplus (tiny arrays only)
__device__ __forceinline__ float sp(float x) {
    return fmaxf(x, 0.0f) + log1pf(expf(-fabsf(x)));
}
// fast softplus via MUFU (rel err ~1e-5; tolerance is 1e-3)
__device__ __forceinline__ float spf(float x) {
    return fmaxf(x, 0.0f) + __logf(1.0f + __expf(-fabsf(x)));
}

// shfl-based block reduce for 256 threads; result valid in thread 0
__device__ __forceinline__ float blockReduce256s(float v) {
    __shared__ float red[8];
    #pragma unroll
    for (int s = 16; s; s >>= 1) v += __shfl_down_sync(0xffffffffu, v, s);
    if ((threadIdx.x & 31) == 0) red[threadIdx.x >> 5] = v;
    __syncthreads();
    if (threadIdx.x < 8) {
        v = red[threadIdx.x];
        #pragma unroll
        for (int s = 4; s; s >>= 1) v += __shfl_down_sync(0xffu, v, s);
    }
    return v;
}

// ---------------- k_prep ----------------
// blocks [0,64): gwsA/gmA tables + gw KL.  block 64: small KL + bias + bucketing.
__global__ void __launch_bounds__(256)
k_prep(const float* __restrict__ gwmu, const float* __restrict__ gwrho,
       const float* __restrict__ gbmu, const float* __restrict__ gbrho,
       const float* __restrict__ rbmu, const float* __restrict__ rbrho,
       const float* __restrict__ alpha, const float* __restrict__ beta,
       const int* __restrict__ gids) {
    int bid = blockIdx.x;
    int tid = threadIdx.x;

    if (bid < N_GW_BLOCKS) {
        int idx = bid * 256 + tid;                  // float4 index over O*I/4
        int i4 = idx & (NI / 4 - 1);
        float4 gm = ((const float4*)gwmu)[idx];
        float4 gr = ((const float4*)gwrho)[idx];
        float4 av = ((const float4*)alpha)[i4];
        float4 bv = ((const float4*)beta)[i4];
        float4 ga, gA;
        float kl = 0.0f;
        #pragma unroll
        for (int c = 0; c < 4; c++) {
            float gmv = (c==0)?gm.x:(c==1)?gm.y:(c==2)?gm.z:gm.w;
            float grv = (c==0)?gr.x:(c==1)?gr.y:(c==2)?gr.z:gr.w;
            float avv = (c==0)?av.x:(c==1)?av.y:(c==2)?av.z:av.w;
            float bvv = (c==0)?bv.x:(c==1)?bv.y:(c==2)?bv.z:bv.w;
            float ai = spf(avv) * spf(bvv);
            float gs = spf(grv);
            float lgs = __logf(gs);
            kl += (-lgs + (gs * gs + gmv * gmv) * 0.5f - 0.5f)
                + (-1.41893853320467f - lgs + (lgs * lgs + gs * gs) * 0.5f);
            float gaV = ai * gs;
            float gAV = ai * gmv;
            if (c==0){ga.x=gaV;gA.x=gAV;} else if(c==1){ga.y=gaV;gA.y=gAV;}
            else if (c==2){ga.z=gaV;gA.z=gAV;} else {ga.w=gaV;gA.w=gAV;}
        }
        ((float4*)d_gwsA)[idx] = ga;
        ((float4*)d_gmA)[idx] = gA;
        float tot = blockReduce256s(kl);
        if (tid == 0) d_pgw[bid] = tot;

    } else {
        __shared__ int cnt[NG];
        __shared__ int off[NG];
        float kl = 0.0f;

        kl += sp(alpha[tid]) + sp(beta[tid]);

        float s  = sp(gbrho[tid]);
        float ls = logf(s);
        kl += -1.41893853320467f - ls + (ls * ls + s * s) * 0.5f;

        for (int k = tid; k < NG * NO; k += 256) {
            d_biasM[k] = fmaf(s, rbmu[k], gbmu[tid]);
            d_biasS[k] = s * spf(rbrho[k]);
        }

        float tot = blockReduce256s(kl);
        if (tid == 0) d_kl0 = tot;

        if (tid < NG) cnt[tid] = 0;
        __syncthreads();
        for (int b = tid; b < NB; b += 256)
            atomicAdd(&cnt[gids[b]], 1);
        __syncthreads();
        if (tid == 0) {
            int acc = 0;
            for (int g = 0; g < NG; g++) {
                off[g] = acc; d_goff[g] = acc; acc += cnt[g];
            }
            d_goff[NG] = acc;
        }
        __syncthreads();
        if (tid < NG) cnt[tid] = 0;
        __syncthreads();
        for (int b = tid; b < NB; b += 256) {
            int g = gids[b];
            int r = atomicAdd(&cnt[g], 1);
            d_perm[off[g] + r] = b;
        }
    }
}

// ---------------- k_main: persistent blocks + tile queue + pipelined MLP4 ----------------
// grid = NBLK persistent blocks; tiles t in [0, NTILES): zc = t&3, oy = (t>>2)&15, g = t>>6.
__global__ void __launch_bounds__(256, 4)
k_main(const float* __restrict__ epsw, const float* __restrict__ epsb,
       const float* __restrict__ x,
       const float* __restrict__ rwmu, const float* __restrict__ rwrho,
       float* __restrict__ out, float* __restrict__ klout) {
    __shared__ __align__(16) float sS[OT * NI];
    __shared__ __align__(16) float sM[OT * NI];
    __shared__ float sbM[OT];
    __shared__ float sbS[OT];
    __shared__ float stageA[8][OT];
    __shared__ float stageB[8][OT];
    __shared__ int s_tile;
    __shared__ unsigned s_win;

    int tid = threadIdx.x;
    int warp = tid >> 5, lane = tid & 31;
    const float4* e4 = (const float4*)epsw;
    const float4* x4 = (const float4*)x;

    int t = blockIdx.x;
    while (t < NTILES) {
        int zc = t & (BCH - 1);
        int oy = (t >> 2) & (N_OT - 1);
        int g  = t >> 6;
        int ob = oy * OT;

        // ---- stage ard-folded M/S tile; zc==0 tile also does rw KL ----
        const float4* rm4 = (const float4*)(rwmu + ((size_t)g * NO + ob) * NI);
        const float4* rr4 = (const float4*)(rwrho + ((size_t)g * NO + ob) * NI);
        const float4* ga4 = (const float4*)(d_gwsA + (size_t)ob * NI);
        const float4* gA4 = (const float4*)(d_gmA + (size_t)ob * NI);

        bool dokl = (zc == 0);
        float kl = 0.0f;

        #pragma unroll 1
        for (int k = tid; k < OT * NI / 4; k += 256) {
            float4 rm = rm4[k];
            float4 rr = rr4[k];
            float4 ga = ga4[k];
            float4 gA = gA4[k];
            float4 Mv, Sv;
            #pragma unroll
            for (int c = 0; c < 4; c++) {
                float rmv = (c==0)?rm.x:(c==1)?rm.y:(c==2)?rm.z:rm.w;
                float rrv = (c==0)?rr.x:(c==1)?rr.y:(c==2)?rr.z:rr.w;
                float gav = (c==0)?ga.x:(c==1)?ga.y:(c==2)?ga.z:ga.w;
                float gAv = (c==0)?gA.x:(c==1)?gA.y:(c==2)?gA.z:gA.w;
                float rs = spf(rrv);
                float Svv = gav * rs;
                float Mvv = fmaf(gav, rmv, gAv);
                if (c==0){Sv.x=Svv;Mv.x=Mvv;} else if(c==1){Sv.y=Svv;Mv.y=Mvv;}
                else if (c==2){Sv.z=Svv;Mv.z=Mvv;} else {Sv.w=Svv;Mv.w=Mvv;}
                if (dokl) {
                    float lrs = __logf(rs);
                    kl += -1.41893853320467f - lrs + (rs * rs + rmv * rmv) * 0.5f;
                }
            }
            ((float4*)sS)[k] = Sv;
            ((float4*)sM)[k] = Mv;
        }
        if (dokl) {
            float tot = blockReduce256s(kl);
            if (tid == 0) d_pkl[g * N_OT + oy] = tot;
        }
        if (tid < OT) {
            sbM[tid] = d_biasM[g * NO + ob + tid];
            sbS[tid] = d_biasS[g * NO + ob + tid];
        }
        __syncthreads();

        int start = d_goff[g];
        int cnt   = d_goff[g + 1] - start;
        int c0 = start + (cnt * zc) / BCH;
        int c1 = start + (cnt * (zc + 1)) / BCH;

        int si = c0 + warp;
        if (si < c1) {
            int bcur = d_perm[si];
            const float4* ep = e4 + ((size_t)bcur * NO + ob) * (NI / 4);
            float4 e00 = __ldcs(ep + lane);
            float4 e01 = __ldcs(ep + lane + 32);
            float4 e10 = __ldcs(ep + (NI / 4) + lane);
            float4 e11 = __ldcs(ep + (NI / 4) + lane + 32);
            const float4* xp = x4 + (size_t)bcur * (NI / 4);
            float4 x0 = xp[lane];
            float4 x1 = xp[lane + 32];

            while (true) {
                int bout = bcur;
                int snext = si + 8;
                int bnext = (snext < c1) ? d_perm[snext] : 0;

                #pragma unroll 1
                for (int ol = 0; ol < OT; ol += 2) {
                    const float4* SpA = (const float4*)(sS + ol * NI);
                    const float4* MpA = (const float4*)(sM + ol * NI);
                    float4 s0 = SpA[lane], m0 = MpA[lane];
                    float4 s1 = SpA[lane + 32], m1 = MpA[lane + 32];

                    float accA;
                    accA = fmaf(fmaf(s0.x, e00.x, m0.x), x0.x, 0.0f);
                    accA = fmaf(fmaf(s0.y, e00.y, m0.y), x0.y, accA);
                    accA = fmaf(fmaf(s0.z, e00.z, m0.z), x0.z, accA);
                    accA = fmaf(fmaf(s0.w, e00.w, m0.w), x0.w, accA);
                    accA = fmaf(fmaf(s1.x, e01.x, m1.x), x1.x, accA);
                    accA = fmaf(fmaf(s1.y, e01.y, m1.y), x1.y, accA);
                    accA = fmaf(fmaf(s1.z, e01.z, m1.z), x1.z, accA);
                    accA = fmaf(fmaf(s1.w, e01.w, m1.w), x1.w, accA);

                    const float4* SpB = (const float4*)(sS + (ol + 1) * NI);
                    const float4* MpB = (const float4*)(sM + (ol + 1) * NI);
                    s0 = SpB[lane]; m0 = MpB[lane];
                    s1 = SpB[lane + 32]; m1 = MpB[lane + 32];

                    float accB;
                    accB = fmaf(fmaf(s0.x, e10.x, m0.x), x0.x, 0.0f);
                    accB = fmaf(fmaf(s0.y, e10.y, m0.y), x0.y, accB);
                    accB = fmaf(fmaf(s0.z, e10.z, m0.z), x0.z, accB);
                    accB = fmaf(fmaf(s0.w, e10.w, m0.w), x0.w, accB);
                    accB = fmaf(fmaf(s1.x, e11.x, m1.x), x1.x, accB);
                    accB = fmaf(fmaf(s1.y, e11.y, m1.y), x1.y, accB);
                    accB = fmaf(fmaf(s1.z, e11.z, m1.z), x1.z, accB);
                    accB = fmaf(fmaf(s1.w, e11.w, m1.w), x1.w, accB);

                    // prefetch next ol-pair / next sample BEFORE shfl tail (WAR reuse)
                    if (ol + 2 < OT) {
                        const float4* epn = ep + (ol + 2) * (NI / 4);
                        e00 = __ldcs(epn + lane);
                        e01 = __ldcs(epn + lane + 32);
                        e10 = __ldcs(epn + (NI / 4) + lane);
                        e11 = __ldcs(epn + (NI / 4) + lane + 32);
                    } else if (snext < c1) {
                        ep = e4 + ((size_t)bnext * NO + ob) * (NI / 4);
                        e00 = __ldcs(ep + lane);
                        e01 = __ldcs(ep + lane + 32);
                        e10 = __ldcs(ep + (NI / 4) + lane);
                        e11 = __ldcs(ep + (NI / 4) + lane + 32);
                        const float4* xpn = x4 + (size_t)bnext * (NI / 4);
                        x0 = xpn[lane];
                        x1 = xpn[lane + 32];
                    }

                    // 4-level half-reductions: lane0 = sum(0..15), lane16 = sum(16..31)
                    #pragma unroll
                    for (int o2 = 8; o2; o2 >>= 1) {
                        accA += __shfl_down_sync(0xffffffffu, accA, o2);
                        accB += __shfl_down_sync(0xffffffffu, accB, o2);
                    }
                    if (lane == 0) {
                        stageA[warp][ol] = accA;
                        stageA[warp][ol + 1] = accB;
                    } else if (lane == 16) {
                        stageB[warp][ol] = accA;
                        stageB[warp][ol + 1] = accB;
                    }
                }
                __syncwarp();

                if (lane < OT) {
                    float bo = fmaf(sbS[lane], epsb[(size_t)bout * NO + ob + lane], sbM[lane]);
                    out[(size_t)bout * NO + ob + lane] =
                        stageA[warp][lane] + stageB[warp][lane] + bo;
                }
                __syncwarp();

                if (snext >= c1) break;
                si = snext;
                bcur = bnext;
            }
        }

        // ---- pop next tile (also serves as SMEM-reuse barrier) ----
        if (tid == 0) s_tile = NBLK + (int)atomicAdd(&d_work, 1u);
        __syncthreads();
        t = s_tile;
    }

    // ---- deterministic KL finalize: last block reduces fixed-order partials ----
    if (tid == 0) {
        __threadfence();
        s_win = (atomicAdd(&d_done, 1u) == NBLK - 1) ? 1u : 0u;
    }
    __syncthreads();
    if (s_win) {
        __threadfence();
        if (tid < 32) {
            float v = (tid == 0) ? d_kl0 : 0.0f;
            for (int k = tid; k < N_PKL; k += 32) v += d_pkl[k];
            for (int k = tid; k < N_GW_BLOCKS; k += 32) v += d_pgw[k];
            #pragma unroll
            for (int o2 = 16; o2; o2 >>= 1) v += __shfl_down_sync(0xffffffffu, v, o2);
            if (tid == 0) {
                *klout = v;
                d_done = 0;   // reset for next graph replay
                d_work = 0;
            }
        }
    }
}

// ---------------- launch ----------------
extern "C" void kernel_launch(void* const* d_in, const int* in_sizes, int n_in,
                              void* d_out, int out_size) {
    const float* x     = (const float*)d_in[0];
    const float* gwmu  = (const float*)d_in[1];
    const float* gwrho = (const float*)d_in[2];
    const float* gbmu  = (const float*)d_in[3];
    const float* gbrho = (const float*)d_in[4];
    const float* rwmu  = (const float*)d_in[5];
    const float* rwrho = (const float*)d_in[6];
    const float* rbmu  = (const float*)d_in[7];
    const float* rbrho = (const float*)d_in[8];
    const float* alpha = (const float*)d_in[9];
    const float* beta  = (const float*)d_in[10];
    const float* epsw  = (const float*)d_in[11];
    const float* epsb  = (const float*)d_in[12];
    const int*   gids  = (const int*)d_in[13];

    float* out   = (float*)d_out;
    float* klout = out + (out_size - 1);

    k_prep<<<PREP_BLOCKS, 256>>>(gwmu, gwrho, gbmu, gbrho,
                                 rbmu, rbrho, alpha, beta, gids);

    k_main<<<NBLK, 256>>>(epsw, epsb, x, rwmu, rwrho, out, klout);
}